// round 1
// baseline (speedup 1.0000x reference)
#include <cuda_runtime.h>
#include <cuda_bf16.h>
#include <math.h>

#define BN 65536
#define DD 1024
#define EE 16
#define HH1 128
#define HH2 64
#define RR1 64
#define RR2 32
#define EPSV 1e-5f

// ---------------- device scratch (sanctioned __device__ globals) ----------------
__device__ __nv_bfloat16 g_xb[(size_t)BN * DD];        // x in bf16 (128 MB)
__device__ __nv_bfloat16 g_rW1b[DD * RR1];             // folded router W1 (bf16)
__device__ float         g_rb1eff[RR1];
__device__ __nv_bfloat16 g_eW1b[(size_t)EE * DD * HH1]; // folded expert W1 (bf16, 4 MB)
__device__ float         g_eb1eff[EE * HH1];
__device__ __nv_bfloat16 g_eW2b[EE * HH1 * HH2];

// ---------------- helpers ----------------
__device__ __forceinline__ unsigned cvta_s(const void* p) {
    return (unsigned)__cvta_generic_to_shared(p);
}

__device__ __forceinline__ void ldm_x4(unsigned r[4], unsigned addr) {
    asm volatile("ldmatrix.sync.aligned.m8n8.x4.shared.b16 {%0,%1,%2,%3}, [%4];"
                 : "=r"(r[0]), "=r"(r[1]), "=r"(r[2]), "=r"(r[3]) : "r"(addr));
}
__device__ __forceinline__ void ldm_x4t(unsigned r[4], unsigned addr) {
    asm volatile("ldmatrix.sync.aligned.m8n8.x4.trans.shared.b16 {%0,%1,%2,%3}, [%4];"
                 : "=r"(r[0]), "=r"(r[1]), "=r"(r[2]), "=r"(r[3]) : "r"(addr));
}
__device__ __forceinline__ void mma16816(float d[4], const unsigned a[4],
                                         unsigned b0, unsigned b1) {
    asm volatile(
        "mma.sync.aligned.m16n8k16.row.col.f32.bf16.bf16.f32 "
        "{%0,%1,%2,%3}, {%4,%5,%6,%7}, {%8,%9}, {%0,%1,%2,%3};"
        : "+f"(d[0]), "+f"(d[1]), "+f"(d[2]), "+f"(d[3])
        : "r"(a[0]), "r"(a[1]), "r"(a[2]), "r"(a[3]), "r"(b0), "r"(b1));
}
__device__ __forceinline__ unsigned packbf(float a, float b) {
    __nv_bfloat162 t = __floats2bfloat162_rn(a, b);
    return *reinterpret_cast<unsigned*>(&t);
}

// ---------------- prep kernels ----------------
__global__ void k_conv_x(const float* __restrict__ x) {
    size_t i = ((size_t)blockIdx.x * 256 + threadIdx.x) * 8;
    float4 v0 = *(const float4*)(x + i);
    float4 v1 = *(const float4*)(x + i + 4);
    uint4 u;
    u.x = packbf(v0.x, v0.y); u.y = packbf(v0.z, v0.w);
    u.z = packbf(v1.x, v1.y); u.w = packbf(v1.z, v1.w);
    *(uint4*)(g_xb + i) = u;
}

__global__ void k_fold_router_w(const float* __restrict__ rW1,
                                const float* __restrict__ g, const float* __restrict__ v) {
    int i = blockIdx.x * 256 + threadIdx.x;   // DD*RR1 = 65536
    int d = i >> 6;
    float rs = g[d] * rsqrtf(v[d] + EPSV);
    g_rW1b[i] = __float2bfloat16(rW1[i] * rs);
}

__global__ void k_fold_router_b(const float* __restrict__ rW1, const float* __restrict__ g,
                                const float* __restrict__ be, const float* __restrict__ mn,
                                const float* __restrict__ v, const float* __restrict__ rb1) {
    int h = blockIdx.x;           // RR1 blocks
    int t = threadIdx.x;
    float s = 0.f;
    for (int d = t; d < DD; d += 256) {
        float rs = g[d] * rsqrtf(v[d] + EPSV);
        float sh = be[d] - mn[d] * rs;
        s += sh * rW1[d * RR1 + h];
    }
    __shared__ float red[256];
    red[t] = s; __syncthreads();
    for (int o = 128; o; o >>= 1) { if (t < o) red[t] += red[t + o]; __syncthreads(); }
    if (!t) g_rb1eff[h] = rb1[h] + red[0];
}

__global__ void k_fold_expert_w(const float* __restrict__ eW1,
                                const float* __restrict__ g, const float* __restrict__ v) {
    int i = blockIdx.x * 256 + threadIdx.x;   // EE*DD*HH1 = 2M
    int ed = i >> 7;                          // e*DD + d
    float sc = g[ed] * rsqrtf(v[ed] + EPSV);
    g_eW1b[i] = __float2bfloat16(eW1[i] * sc);
}

__global__ void k_fold_expert_b(const float* __restrict__ eW1, const float* __restrict__ g,
                                const float* __restrict__ be, const float* __restrict__ mn,
                                const float* __restrict__ v, const float* __restrict__ eb1) {
    int b = blockIdx.x;                       // EE*HH1 = 2048
    int e = b >> 7, h = b & 127;
    int t = threadIdx.x;
    float s = 0.f;
    for (int d = t; d < DD; d += 256) {
        int ed = e * DD + d;
        float sc = g[ed] * rsqrtf(v[ed] + EPSV);
        float sh = be[ed] - mn[ed] * sc;
        s += sh * eW1[(size_t)ed * HH1 + h];
    }
    __shared__ float red[256];
    red[t] = s; __syncthreads();
    for (int o = 128; o; o >>= 1) { if (t < o) red[t] += red[t + o]; __syncthreads(); }
    if (!t) g_eb1eff[b] = eb1[b] + red[0];
}

__global__ void k_conv_w2(const float* __restrict__ eW2) {
    int i = blockIdx.x * 256 + threadIdx.x;   // 131072
    g_eW2b[i] = __float2bfloat16(eW2[i]);
}

// ---------------- expert kernel ----------------
// grid: (EE, BN/128); block 256 threads (8 warps: 4 m x 2 n)
__global__ void __launch_bounds__(256) expert_kernel(const float* __restrict__ eb2,
                                                     const float* __restrict__ eW3,
                                                     const float* __restrict__ eb3,
                                                     float* __restrict__ out) {
    __shared__ __align__(16) char sm[39424];
    __nv_bfloat16* Xs  = (__nv_bfloat16*)sm;             // [128][40]
    __nv_bfloat16* Ws  = (__nv_bfloat16*)(sm + 10240);   // [32][136]
    __nv_bfloat16* H1s = (__nv_bfloat16*)sm;             // [128][136]
    __nv_bfloat16* W2c = (__nv_bfloat16*)(sm + 34816);   // [32][72]
    float*         H2s = (float*)sm;                     // [128][67]

    const int e   = blockIdx.x;
    const int m0  = blockIdx.y * 128;
    const int tid = threadIdx.x;
    const int lane = tid & 31;
    const int w    = tid >> 5;
    const int wm   = w & 3;   // row quad (32 rows)
    const int wn   = w >> 2;  // col half (64 cols)

    float acc[2][8][4];
#pragma unroll
    for (int a = 0; a < 2; ++a)
#pragma unroll
        for (int b = 0; b < 8; ++b)
#pragma unroll
            for (int c = 0; c < 4; ++c) acc[a][b][c] = 0.f;

    const __nv_bfloat16* W1p = g_eW1b + (size_t)e * (DD * HH1);
    const __nv_bfloat16* Xp  = g_xb + (size_t)m0 * DD;

    const int xr = tid >> 1, xc = (tid & 1) * 16;
    const int wr = tid >> 3, wc = (tid & 7) * 16;

    for (int k0 = 0; k0 < DD; k0 += 32) {
        // stage X tile [128 x 32] bf16
        const uint4* xsrc = (const uint4*)(Xp + (size_t)xr * DD + k0 + xc);
        uint4 xv0 = xsrc[0], xv1 = xsrc[1];
        *(uint4*)(Xs + xr * 40 + xc)     = xv0;
        *(uint4*)(Xs + xr * 40 + xc + 8) = xv1;
        // stage W1 tile [32 x 128] bf16
        const uint4* wsrc = (const uint4*)(W1p + (size_t)(k0 + wr) * HH1 + wc);
        uint4 wv0 = wsrc[0], wv1 = wsrc[1];
        *(uint4*)(Ws + wr * 136 + wc)     = wv0;
        *(uint4*)(Ws + wr * 136 + wc + 8) = wv1;
        __syncthreads();
#pragma unroll
        for (int kk = 0; kk < 2; ++kk) {
            unsigned a0[4], a1[4];
            const int ar = wm * 32 + (lane & 15);
            const int ac = kk * 16 + (lane >> 4) * 8;
            ldm_x4(a0, cvta_s(Xs + ar * 40 + ac));
            ldm_x4(a1, cvta_s(Xs + (ar + 16) * 40 + ac));
            const int br = kk * 16 + (lane & 15);
#pragma unroll
            for (int p = 0; p < 4; ++p) {
                unsigned bb[4];
                ldm_x4t(bb, cvta_s(Ws + br * 136 + wn * 64 + p * 16 + (lane >> 4) * 8));
                mma16816(acc[0][2 * p],     a0, bb[0], bb[1]);
                mma16816(acc[1][2 * p],     a1, bb[0], bb[1]);
                mma16816(acc[0][2 * p + 1], a0, bb[2], bb[3]);
                mma16816(acc[1][2 * p + 1], a1, bb[2], bb[3]);
            }
        }
        __syncthreads();
    }

    // epilogue GEMM1: bias + relu -> H1s (bf16); stage W2 chunk 0
    {
        const float* b1 = g_eb1eff + e * HH1;
#pragma unroll
        for (int mi = 0; mi < 2; ++mi)
#pragma unroll
            for (int nj = 0; nj < 8; ++nj) {
                int r = wm * 32 + mi * 16 + (lane >> 2);
                int c = wn * 64 + nj * 8 + (lane & 3) * 2;
                float ba = b1[c], bbv = b1[c + 1];
                float v0 = fmaxf(acc[mi][nj][0] + ba,  0.f);
                float v1 = fmaxf(acc[mi][nj][1] + bbv, 0.f);
                float v2 = fmaxf(acc[mi][nj][2] + ba,  0.f);
                float v3 = fmaxf(acc[mi][nj][3] + bbv, 0.f);
                *(__nv_bfloat162*)(H1s + r * 136 + c)       = __floats2bfloat162_rn(v0, v1);
                *(__nv_bfloat162*)(H1s + (r + 8) * 136 + c) = __floats2bfloat162_rn(v2, v3);
            }
    }
    const __nv_bfloat16* W2p = g_eW2b + e * (HH1 * HH2);
    const int w2r = tid >> 3, w2c = (tid & 7) * 8;
    *(uint4*)(W2c + w2r * 72 + w2c) = *(const uint4*)(W2p + w2r * HH2 + w2c);
    __syncthreads();

    // GEMM2: [128x128] @ [128x64], K streamed in 4 chunks of 32
    float acc2[2][4][4];
#pragma unroll
    for (int a = 0; a < 2; ++a)
#pragma unroll
        for (int b = 0; b < 4; ++b)
#pragma unroll
            for (int c = 0; c < 4; ++c) acc2[a][b][c] = 0.f;

    for (int ch = 0; ch < 4; ++ch) {
#pragma unroll
        for (int kk = 0; kk < 2; ++kk) {
            unsigned a0[4], a1[4];
            const int ar = wm * 32 + (lane & 15);
            const int ac = ch * 32 + kk * 16 + (lane >> 4) * 8;
            ldm_x4(a0, cvta_s(H1s + ar * 136 + ac));
            ldm_x4(a1, cvta_s(H1s + (ar + 16) * 136 + ac));
            const int br = kk * 16 + (lane & 15);
#pragma unroll
            for (int p = 0; p < 2; ++p) {
                unsigned bb[4];
                ldm_x4t(bb, cvta_s(W2c + br * 72 + wn * 32 + p * 16 + (lane >> 4) * 8));
                mma16816(acc2[0][2 * p],     a0, bb[0], bb[1]);
                mma16816(acc2[1][2 * p],     a1, bb[0], bb[1]);
                mma16816(acc2[0][2 * p + 1], a0, bb[2], bb[3]);
                mma16816(acc2[1][2 * p + 1], a1, bb[2], bb[3]);
            }
        }
        if (ch < 3) {
            __syncthreads();
            *(uint4*)(W2c + w2r * 72 + w2c) =
                *(const uint4*)(W2p + ((ch + 1) * 32 + w2r) * HH2 + w2c);
            __syncthreads();
        }
    }
    __syncthreads();

    // epilogue GEMM2: bias + relu -> H2s (fp32, overwrites H1s region)
    {
        const float* b2 = eb2 + e * HH2;
#pragma unroll
        for (int mi = 0; mi < 2; ++mi)
#pragma unroll
            for (int nj = 0; nj < 4; ++nj) {
                int r = wm * 32 + mi * 16 + (lane >> 2);
                int c = wn * 32 + nj * 8 + (lane & 3) * 2;
                float ba = b2[c], bbv = b2[c + 1];
                H2s[r * 67 + c]           = fmaxf(acc2[mi][nj][0] + ba,  0.f);
                H2s[r * 67 + c + 1]       = fmaxf(acc2[mi][nj][1] + bbv, 0.f);
                H2s[(r + 8) * 67 + c]     = fmaxf(acc2[mi][nj][2] + ba,  0.f);
                H2s[(r + 8) * 67 + c + 1] = fmaxf(acc2[mi][nj][3] + bbv, 0.f);
            }
    }
    __syncthreads();

    // GEMM3 (dot with W3[64]) + sigmoid
    {
        int row = tid >> 1, half = tid & 1;
        const float* w3 = eW3 + e * HH2 + half * 32;
        const float* hp = H2s + row * 67 + half * 32;
        float s = 0.f;
#pragma unroll
        for (int i = 0; i < 32; ++i) s += hp[i] * w3[i];
        s += __shfl_xor_sync(0xffffffffu, s, 1);
        if (half == 0) {
            float z = s + eb3[e];
            out[(size_t)BN * 17 + (size_t)(m0 + row) * EE + e] = 1.f / (1.f + expf(-z));
        }
    }
}

// ---------------- router kernel ----------------
// grid: BN/128; block 256 (8 warps: 4 m x 2 n, N=64)
__global__ void __launch_bounds__(256) router_kernel(const float* __restrict__ rW2,
                                                     const float* __restrict__ rb2,
                                                     const float* __restrict__ rW3,
                                                     const float* __restrict__ rb3,
                                                     float* __restrict__ out) {
    __shared__ __align__(16) char sm[44736];
    __nv_bfloat16* Xs = (__nv_bfloat16*)sm;            // [128][40]
    __nv_bfloat16* Wr = (__nv_bfloat16*)(sm + 10240);  // [32][72]
    float* H1r  = (float*)sm;                          // [128][67]
    float* rW2s = (float*)(sm + 34304);                // [64*32]
    float* rW3s = (float*)(sm + 42496);                // [32*16]
    float* rb2s = (float*)(sm + 44544);                // [32]
    float* rb3s = (float*)(sm + 44672);                // [16]

    const int m0  = blockIdx.x * 128;
    const int tid = threadIdx.x;
    const int lane = tid & 31;
    const int w    = tid >> 5;
    const int wm   = w & 3;
    const int wn   = w >> 2;

    for (int i = tid; i < RR1 * RR2; i += 256) rW2s[i] = rW2[i];
    for (int i = tid; i < RR2 * EE;  i += 256) rW3s[i] = rW3[i];
    if (tid < RR2) rb2s[tid] = rb2[tid];
    if (tid < EE)  rb3s[tid] = rb3[tid];

    float acc[2][4][4];
#pragma unroll
    for (int a = 0; a < 2; ++a)
#pragma unroll
        for (int b = 0; b < 4; ++b)
#pragma unroll
            for (int c = 0; c < 4; ++c) acc[a][b][c] = 0.f;

    const __nv_bfloat16* Xp = g_xb + (size_t)m0 * DD;
    const int xr = tid >> 1, xc = (tid & 1) * 16;
    const int rr = tid >> 3, rc = (tid & 7) * 8;

    for (int k0 = 0; k0 < DD; k0 += 32) {
        const uint4* xsrc = (const uint4*)(Xp + (size_t)xr * DD + k0 + xc);
        uint4 xv0 = xsrc[0], xv1 = xsrc[1];
        *(uint4*)(Xs + xr * 40 + xc)     = xv0;
        *(uint4*)(Xs + xr * 40 + xc + 8) = xv1;
        *(uint4*)(Wr + rr * 72 + rc) = *(const uint4*)(g_rW1b + (k0 + rr) * RR1 + rc);
        __syncthreads();
#pragma unroll
        for (int kk = 0; kk < 2; ++kk) {
            unsigned a0[4], a1[4];
            const int ar = wm * 32 + (lane & 15);
            const int ac = kk * 16 + (lane >> 4) * 8;
            ldm_x4(a0, cvta_s(Xs + ar * 40 + ac));
            ldm_x4(a1, cvta_s(Xs + (ar + 16) * 40 + ac));
            const int br = kk * 16 + (lane & 15);
#pragma unroll
            for (int p = 0; p < 2; ++p) {
                unsigned bb[4];
                ldm_x4t(bb, cvta_s(Wr + br * 72 + wn * 32 + p * 16 + (lane >> 4) * 8));
                mma16816(acc[0][2 * p],     a0, bb[0], bb[1]);
                mma16816(acc[1][2 * p],     a1, bb[0], bb[1]);
                mma16816(acc[0][2 * p + 1], a0, bb[2], bb[3]);
                mma16816(acc[1][2 * p + 1], a1, bb[2], bb[3]);
            }
        }
        __syncthreads();
    }

    // bias + relu -> H1r (fp32)
#pragma unroll
    for (int mi = 0; mi < 2; ++mi)
#pragma unroll
        for (int nj = 0; nj < 4; ++nj) {
            int r = wm * 32 + mi * 16 + (lane >> 2);
            int c = wn * 32 + nj * 8 + (lane & 3) * 2;
            float ba = g_rb1eff[c], bbv = g_rb1eff[c + 1];
            H1r[r * 67 + c]           = fmaxf(acc[mi][nj][0] + ba,  0.f);
            H1r[r * 67 + c + 1]       = fmaxf(acc[mi][nj][1] + bbv, 0.f);
            H1r[(r + 8) * 67 + c]     = fmaxf(acc[mi][nj][2] + ba,  0.f);
            H1r[(r + 8) * 67 + c + 1] = fmaxf(acc[mi][nj][3] + bbv, 0.f);
        }
    __syncthreads();

    if (tid < 128) {
        const float* h1 = H1r + tid * 67;
        float h2[RR2];
#pragma unroll 4
        for (int j = 0; j < RR2; ++j) {
            float s = rb2s[j];
            for (int i = 0; i < RR1; ++i) s += h1[i] * rW2s[i * RR2 + j];
            h2[j] = fmaxf(s, 0.f);
        }
        float lg[EE];
#pragma unroll
        for (int t = 0; t < EE; ++t) {
            float s = rb3s[t];
#pragma unroll
            for (int j = 0; j < RR2; ++j) s += h2[j] * rW3s[j * EE + t];
            lg[t] = s;
        }
        float mx = lg[0];
#pragma unroll
        for (int t = 1; t < EE; ++t) mx = fmaxf(mx, lg[t]);
        float ex[EE]; float den = 0.f;
#pragma unroll
        for (int t = 0; t < EE; ++t) { ex[t] = expf(lg[t] - mx); den += ex[t]; }
        float inv = 1.f / den;
        float* o = out + BN + (size_t)(m0 + tid) * EE;
#pragma unroll
        for (int t = 0; t < EE; ++t) o[t] = ex[t] * inv;
    }
}

// ---------------- combine: weighted_pred ----------------
__global__ void combine_kernel(float* __restrict__ out) {
    int i = blockIdx.x * 256 + threadIdx.x;   // BN threads
    const float4* rw = (const float4*)(out + BN + (size_t)i * EE);
    const float4* eo = (const float4*)(out + (size_t)BN * 17 + (size_t)i * EE);
    float s = 0.f;
#pragma unroll
    for (int q = 0; q < 4; ++q) {
        float4 a = rw[q], b = eo[q];
        s += a.x * b.x + a.y * b.y + a.z * b.z + a.w * b.w;
    }
    out[i] = s;
}

// ---------------- launcher ----------------
extern "C" void kernel_launch(void* const* d_in, const int* in_sizes, int n_in,
                              void* d_out, int out_size) {
    const float* x       = (const float*)d_in[0];
    const float* r_gamma = (const float*)d_in[1];
    const float* r_beta  = (const float*)d_in[2];
    const float* r_mean  = (const float*)d_in[3];
    const float* r_var   = (const float*)d_in[4];
    const float* rW1     = (const float*)d_in[5];
    const float* rb1     = (const float*)d_in[6];
    const float* rW2     = (const float*)d_in[7];
    const float* rb2     = (const float*)d_in[8];
    const float* rW3     = (const float*)d_in[9];
    const float* rb3     = (const float*)d_in[10];
    const float* e_gamma = (const float*)d_in[11];
    const float* e_beta  = (const float*)d_in[12];
    const float* e_mean  = (const float*)d_in[13];
    const float* e_var   = (const float*)d_in[14];
    const float* eW1     = (const float*)d_in[15];
    const float* eb1     = (const float*)d_in[16];
    const float* eW2     = (const float*)d_in[17];
    const float* eb2     = (const float*)d_in[18];
    const float* eW3     = (const float*)d_in[19];
    const float* eb3     = (const float*)d_in[20];
    float* out = (float*)d_out;

    k_conv_x<<<(BN * (size_t)DD) / (256 * 8), 256>>>(x);
    k_fold_router_w<<<(DD * RR1) / 256, 256>>>(rW1, r_gamma, r_var);
    k_fold_router_b<<<RR1, 256>>>(rW1, r_gamma, r_beta, r_mean, r_var, rb1);
    k_fold_expert_w<<<(EE * DD * HH1) / 256, 256>>>(eW1, e_gamma, e_var);
    k_fold_expert_b<<<EE * HH1, 256>>>(eW1, e_gamma, e_beta, e_mean, e_var, eb1);
    k_conv_w2<<<(EE * HH1 * HH2) / 256, 256>>>(eW2);

    router_kernel<<<BN / 128, 256>>>(rW2, rb2, rW3, rb3, out);
    expert_kernel<<<dim3(EE, BN / 128), 256>>>(eb2, eW3, eb3, out);
    combine_kernel<<<BN / 256, 256>>>(out);
}

// round 2
// speedup vs baseline: 1.5109x; 1.5109x over previous
#include <cuda_runtime.h>
#include <cuda_bf16.h>
#include <math.h>

#define BN 65536
#define DD 1024
#define EE 16
#define HH1 128
#define HH2 64
#define RR1 64
#define RR2 32
#define EPSV 1e-5f
#define KC 32

// ---------------- device scratch ----------------
__device__ __nv_bfloat16 g_xb[(size_t)BN * DD];
__device__ __nv_bfloat16 g_rW1b[DD * RR1];
__device__ float         g_rb1eff[RR1];
__device__ __nv_bfloat16 g_eW1b[(size_t)EE * DD * HH1];
__device__ float         g_eb1eff[EE * HH1];
__device__ __nv_bfloat16 g_eW2b[EE * HH1 * HH2];

// ---------------- helpers ----------------
__device__ __forceinline__ unsigned cvta_s(const void* p) {
    return (unsigned)__cvta_generic_to_shared(p);
}
__device__ __forceinline__ void cp16(void* s, const void* g) {
    asm volatile("cp.async.cg.shared.global [%0], [%1], 16;\n"
                 :: "r"(cvta_s(s)), "l"(g));
}
__device__ __forceinline__ void cp_commit() {
    asm volatile("cp.async.commit_group;\n");
}
template<int N> __device__ __forceinline__ void cp_wait() {
    asm volatile("cp.async.wait_group %0;\n" :: "n"(N));
}
__device__ __forceinline__ void ldm_x4(unsigned r[4], unsigned addr) {
    asm volatile("ldmatrix.sync.aligned.m8n8.x4.shared.b16 {%0,%1,%2,%3}, [%4];"
                 : "=r"(r[0]), "=r"(r[1]), "=r"(r[2]), "=r"(r[3]) : "r"(addr));
}
__device__ __forceinline__ void ldm_x4t(unsigned r[4], unsigned addr) {
    asm volatile("ldmatrix.sync.aligned.m8n8.x4.trans.shared.b16 {%0,%1,%2,%3}, [%4];"
                 : "=r"(r[0]), "=r"(r[1]), "=r"(r[2]), "=r"(r[3]) : "r"(addr));
}
__device__ __forceinline__ void mma16816(float d[4], const unsigned a[4],
                                         unsigned b0, unsigned b1) {
    asm volatile(
        "mma.sync.aligned.m16n8k16.row.col.f32.bf16.bf16.f32 "
        "{%0,%1,%2,%3}, {%4,%5,%6,%7}, {%8,%9}, {%0,%1,%2,%3};"
        : "+f"(d[0]), "+f"(d[1]), "+f"(d[2]), "+f"(d[3])
        : "r"(a[0]), "r"(a[1]), "r"(a[2]), "r"(a[3]), "r"(b0), "r"(b1));
}
__device__ __forceinline__ unsigned packbf(float a, float b) {
    __nv_bfloat162 t = __floats2bfloat162_rn(a, b);
    return *reinterpret_cast<unsigned*>(&t);
}

// ---------------- prep kernels ----------------
__global__ void k_conv_x(const float* __restrict__ x) {
    size_t i = ((size_t)blockIdx.x * 256 + threadIdx.x) * 8;
    float4 v0 = *(const float4*)(x + i);
    float4 v1 = *(const float4*)(x + i + 4);
    uint4 u;
    u.x = packbf(v0.x, v0.y); u.y = packbf(v0.z, v0.w);
    u.z = packbf(v1.x, v1.y); u.w = packbf(v1.z, v1.w);
    *(uint4*)(g_xb + i) = u;
}

// blocks [0,256): fold rW1 weights; [256,320): fold router bias
__global__ void k_prep_router(const float* __restrict__ rW1, const float* __restrict__ g,
                              const float* __restrict__ be, const float* __restrict__ mn,
                              const float* __restrict__ v, const float* __restrict__ rb1) {
    int b = blockIdx.x, t = threadIdx.x;
    if (b < 256) {
        int i = b * 256 + t;
        int d = i >> 6;
        float rs = g[d] * rsqrtf(v[d] + EPSV);
        g_rW1b[i] = __float2bfloat16(rW1[i] * rs);
    } else {
        int h = b - 256;
        float s = 0.f;
        for (int d = t; d < DD; d += 256) {
            float rs = g[d] * rsqrtf(v[d] + EPSV);
            float sh = be[d] - mn[d] * rs;
            s += sh * rW1[d * RR1 + h];
        }
        __shared__ float red[256];
        red[t] = s; __syncthreads();
        for (int o = 128; o; o >>= 1) { if (t < o) red[t] += red[t + o]; __syncthreads(); }
        if (!t) g_rb1eff[h] = rb1[h] + red[0];
    }
}

// blocks [0,8192): fold eW1; [8192,8704): convert eW2
__global__ void k_prep_expert_w(const float* __restrict__ eW1, const float* __restrict__ g,
                                const float* __restrict__ v, const float* __restrict__ eW2) {
    int b = blockIdx.x, t = threadIdx.x;
    if (b < 8192) {
        int i = b * 256 + t;
        int ed = i >> 7;
        float sc = g[ed] * rsqrtf(v[ed] + EPSV);
        g_eW1b[i] = __float2bfloat16(eW1[i] * sc);
    } else {
        int i = (b - 8192) * 256 + t;
        g_eW2b[i] = __float2bfloat16(eW2[i]);
    }
}

__global__ void k_fold_expert_b(const float* __restrict__ eW1, const float* __restrict__ g,
                                const float* __restrict__ be, const float* __restrict__ mn,
                                const float* __restrict__ v, const float* __restrict__ eb1) {
    int b = blockIdx.x;
    int e = b >> 7, h = b & 127;
    int t = threadIdx.x;
    float s = 0.f;
    for (int d = t; d < DD; d += 256) {
        int ed = e * DD + d;
        float sc = g[ed] * rsqrtf(v[ed] + EPSV);
        float sh = be[ed] - mn[ed] * sc;
        s += sh * eW1[(size_t)ed * HH1 + h];
    }
    __shared__ float red[256];
    red[t] = s; __syncthreads();
    for (int o = 128; o; o >>= 1) { if (t < o) red[t] += red[t + o]; __syncthreads(); }
    if (!t) g_eb1eff[b] = eb1[b] + red[0];
}

// ---------------- router kernel (cp.async pipelined GEMM1) ----------------
__global__ void __launch_bounds__(256) router_kernel(const float* __restrict__ rW2,
                                                     const float* __restrict__ rb2,
                                                     const float* __restrict__ rW3,
                                                     const float* __restrict__ rb3,
                                                     float* __restrict__ out) {
    __shared__ __align__(16) char sm[45248];
    __nv_bfloat16* Xb0 = (__nv_bfloat16*)sm;
    __nv_bfloat16* Xb1 = (__nv_bfloat16*)(sm + 10240);
    __nv_bfloat16* Wr0 = (__nv_bfloat16*)(sm + 20480);
    __nv_bfloat16* Wr1 = (__nv_bfloat16*)(sm + 25088);
    float* H1r  = (float*)sm;                 // [128][67]  (overlaps pipeline bufs)
    float* rW2s = (float*)(sm + 34816);
    float* rW3s = (float*)(sm + 43008);
    float* rb2s = (float*)(sm + 45056);
    float* rb3s = (float*)(sm + 45184);

    const int m0 = blockIdx.x * 128;
    const int tid = threadIdx.x;
    const int lane = tid & 31;
    const int w = tid >> 5;
    const int wm = w & 3;
    const int wn = w >> 2;

    for (int i = tid; i < RR1 * RR2; i += 256) rW2s[i] = rW2[i];
    for (int i = tid; i < RR2 * EE;  i += 256) rW3s[i] = rW3[i];
    if (tid < RR2) rb2s[tid] = rb2[tid];
    if (tid < EE)  rb3s[tid] = rb3[tid];

    const __nv_bfloat16* Xp = g_xb + (size_t)m0 * DD;
    const int x_r = tid >> 2, x_c = (tid & 3) * 8;     // X: 2 ops/thread
    const int r_r = tid >> 3, r_c = (tid & 7) * 8;     // W: 1 op/thread

    __nv_bfloat16* XB[2] = {Xb0, Xb1};
    __nv_bfloat16* WB[2] = {Wr0, Wr1};

    auto issue = [&](int c, int b) {
        const __nv_bfloat16* xs = Xp + (size_t)x_r * DD + c * KC + x_c;
        cp16(XB[b] + x_r * 40 + x_c, xs);
        cp16(XB[b] + (x_r + 64) * 40 + x_c, xs + (size_t)64 * DD);
        cp16(WB[b] + r_r * 72 + r_c, g_rW1b + (c * KC + r_r) * RR1 + r_c);
    };

    float acc[2][4][4];
#pragma unroll
    for (int a = 0; a < 2; ++a)
#pragma unroll
        for (int bq = 0; bq < 4; ++bq)
#pragma unroll
            for (int cq = 0; cq < 4; ++cq) acc[a][bq][cq] = 0.f;

    issue(0, 0); cp_commit();
    issue(1, 1); cp_commit();
    for (int c = 0; c < DD / KC; ++c) {
        cp_wait<1>(); __syncthreads();
        int b = c & 1;
#pragma unroll
        for (int kk = 0; kk < 2; ++kk) {
            unsigned a0[4], a1[4];
            int ar = wm * 32 + (lane & 15), ac = kk * 16 + (lane >> 4) * 8;
            ldm_x4(a0, cvta_s(XB[b] + ar * 40 + ac));
            ldm_x4(a1, cvta_s(XB[b] + (ar + 16) * 40 + ac));
            int br = kk * 16 + (lane & 15);
#pragma unroll
            for (int p = 0; p < 2; ++p) {
                unsigned bb[4];
                ldm_x4t(bb, cvta_s(WB[b] + br * 72 + wn * 32 + p * 16 + (lane >> 4) * 8));
                mma16816(acc[0][2 * p],     a0, bb[0], bb[1]);
                mma16816(acc[1][2 * p],     a1, bb[0], bb[1]);
                mma16816(acc[0][2 * p + 1], a0, bb[2], bb[3]);
                mma16816(acc[1][2 * p + 1], a1, bb[2], bb[3]);
            }
        }
        __syncthreads();
        if (c + 2 < DD / KC) issue(c + 2, b);
        cp_commit();
    }

    // bias + relu -> H1r (fp32)
#pragma unroll
    for (int mi = 0; mi < 2; ++mi)
#pragma unroll
        for (int nj = 0; nj < 4; ++nj) {
            int r = wm * 32 + mi * 16 + (lane >> 2);
            int c = wn * 32 + nj * 8 + (lane & 3) * 2;
            float ba = g_rb1eff[c], bbv = g_rb1eff[c + 1];
            H1r[r * 67 + c]           = fmaxf(acc[mi][nj][0] + ba,  0.f);
            H1r[r * 67 + c + 1]       = fmaxf(acc[mi][nj][1] + bbv, 0.f);
            H1r[(r + 8) * 67 + c]     = fmaxf(acc[mi][nj][2] + ba,  0.f);
            H1r[(r + 8) * 67 + c + 1] = fmaxf(acc[mi][nj][3] + bbv, 0.f);
        }
    __syncthreads();

    if (tid < 128) {
        const float* h1 = H1r + tid * 67;
        float h2[RR2];
#pragma unroll 4
        for (int j = 0; j < RR2; ++j) {
            float s = rb2s[j];
            for (int i = 0; i < RR1; ++i) s += h1[i] * rW2s[i * RR2 + j];
            h2[j] = fmaxf(s, 0.f);
        }
        float lg[EE];
#pragma unroll
        for (int t = 0; t < EE; ++t) {
            float s = rb3s[t];
#pragma unroll
            for (int j = 0; j < RR2; ++j) s += h2[j] * rW3s[j * EE + t];
            lg[t] = s;
        }
        float mx = lg[0];
#pragma unroll
        for (int t = 1; t < EE; ++t) mx = fmaxf(mx, lg[t]);
        float ex[EE]; float den = 0.f;
#pragma unroll
        for (int t = 0; t < EE; ++t) { ex[t] = expf(lg[t] - mx); den += ex[t]; }
        float inv = 1.f / den;
        float* o = out + BN + (size_t)(m0 + tid) * EE;
#pragma unroll
        for (int t = 0; t < EE; ++t) o[t] = ex[t] * inv;
    }
}

// ---------------- expert kernel (cp.async double-buffered) ----------------
// grid: (EE, BN/128); block 256 (8 warps: 4m x 2n)
__global__ void __launch_bounds__(256) expert_kernel(const float* __restrict__ eb2,
                                                     const float* __restrict__ eW3,
                                                     const float* __restrict__ eb3,
                                                     float* __restrict__ out) {
    __shared__ __align__(16) char sm[44032];
    __nv_bfloat16* XB[2] = {(__nv_bfloat16*)sm, (__nv_bfloat16*)(sm + 10240)};
    __nv_bfloat16* WB[2] = {(__nv_bfloat16*)(sm + 20480), (__nv_bfloat16*)(sm + 29184)};
    __nv_bfloat16* H1s = (__nv_bfloat16*)sm;                         // [128][136]
    __nv_bfloat16* W2C[2] = {(__nv_bfloat16*)(sm + 34816), (__nv_bfloat16*)(sm + 39424)};
    float* H2s = (float*)sm;                                         // [128][67]

    const int e  = blockIdx.x;
    const int m0 = blockIdx.y * 128;
    const int tid = threadIdx.x;
    const int lane = tid & 31;
    const int w = tid >> 5;
    const int wm = w & 3;
    const int wn = w >> 2;

    const __nv_bfloat16* W1p = g_eW1b + (size_t)e * (DD * HH1);
    const __nv_bfloat16* Xp  = g_xb + (size_t)m0 * DD;
    const __nv_bfloat16* W2p = g_eW2b + e * (HH1 * HH2);

    const int x_r = tid >> 2,  x_c = (tid & 3) * 8;    // X: 2 ops/thread
    const int w_r = tid >> 4,  w_c = (tid & 15) * 8;   // W1: 2 ops/thread
    const int w2_r = tid >> 3, w2_c = (tid & 7) * 8;   // W2: 1 op/thread

    auto issue = [&](int c, int b) {
        const __nv_bfloat16* xs = Xp + (size_t)x_r * DD + c * KC + x_c;
        cp16(XB[b] + x_r * 40 + x_c, xs);
        cp16(XB[b] + (x_r + 64) * 40 + x_c, xs + (size_t)64 * DD);
        const __nv_bfloat16* ws = W1p + (size_t)(c * KC + w_r) * HH1 + w_c;
        cp16(WB[b] + w_r * 136 + w_c, ws);
        cp16(WB[b] + (w_r + 16) * 136 + w_c, ws + (size_t)16 * HH1);
    };

    float acc[2][8][4];
#pragma unroll
    for (int a = 0; a < 2; ++a)
#pragma unroll
        for (int bq = 0; bq < 8; ++bq)
#pragma unroll
            for (int cq = 0; cq < 4; ++cq) acc[a][bq][cq] = 0.f;

    issue(0, 0); cp_commit();
    issue(1, 1); cp_commit();
    for (int c = 0; c < DD / KC; ++c) {
        cp_wait<1>(); __syncthreads();
        int b = c & 1;
#pragma unroll
        for (int kk = 0; kk < 2; ++kk) {
            unsigned a0[4], a1[4];
            int ar = wm * 32 + (lane & 15), ac = kk * 16 + (lane >> 4) * 8;
            ldm_x4(a0, cvta_s(XB[b] + ar * 40 + ac));
            ldm_x4(a1, cvta_s(XB[b] + (ar + 16) * 40 + ac));
            int br = kk * 16 + (lane & 15);
#pragma unroll
            for (int p = 0; p < 4; ++p) {
                unsigned bb[4];
                ldm_x4t(bb, cvta_s(WB[b] + br * 136 + wn * 64 + p * 16 + (lane >> 4) * 8));
                mma16816(acc[0][2 * p],     a0, bb[0], bb[1]);
                mma16816(acc[1][2 * p],     a1, bb[0], bb[1]);
                mma16816(acc[0][2 * p + 1], a0, bb[2], bb[3]);
                mma16816(acc[1][2 * p + 1], a1, bb[2], bb[3]);
            }
        }
        __syncthreads();
        if (c + 2 < DD / KC) issue(c + 2, b);
        cp_commit();
    }

    // epilogue GEMM1: bias + relu -> H1s (bf16)
    {
        const float* b1 = g_eb1eff + e * HH1;
#pragma unroll
        for (int mi = 0; mi < 2; ++mi)
#pragma unroll
            for (int nj = 0; nj < 8; ++nj) {
                int r = wm * 32 + mi * 16 + (lane >> 2);
                int c = wn * 64 + nj * 8 + (lane & 3) * 2;
                float ba = b1[c], bbv = b1[c + 1];
                float v0 = fmaxf(acc[mi][nj][0] + ba,  0.f);
                float v1 = fmaxf(acc[mi][nj][1] + bbv, 0.f);
                float v2 = fmaxf(acc[mi][nj][2] + ba,  0.f);
                float v3 = fmaxf(acc[mi][nj][3] + bbv, 0.f);
                *(__nv_bfloat162*)(H1s + r * 136 + c)       = __floats2bfloat162_rn(v0, v1);
                *(__nv_bfloat162*)(H1s + (r + 8) * 136 + c) = __floats2bfloat162_rn(v2, v3);
            }
    }

    // GEMM2: [128x128]@[128x64], W2 streamed in 4 chunks of K=32, double-buffered
    auto issueW2 = [&](int ch, int b) {
        cp16(W2C[b] + w2_r * 72 + w2_c, W2p + (size_t)(ch * 32 + w2_r) * HH2 + w2_c);
    };

    float acc2[2][4][4];
#pragma unroll
    for (int a = 0; a < 2; ++a)
#pragma unroll
        for (int bq = 0; bq < 4; ++bq)
#pragma unroll
            for (int cq = 0; cq < 4; ++cq) acc2[a][bq][cq] = 0.f;

    issueW2(0, 0); cp_commit();
    issueW2(1, 1); cp_commit();
    for (int ch = 0; ch < 4; ++ch) {
        cp_wait<1>(); __syncthreads();
        int b = ch & 1;
#pragma unroll
        for (int kk = 0; kk < 2; ++kk) {
            unsigned a0[4], a1[4];
            int ar = wm * 32 + (lane & 15), ac = ch * 32 + kk * 16 + (lane >> 4) * 8;
            ldm_x4(a0, cvta_s(H1s + ar * 136 + ac));
            ldm_x4(a1, cvta_s(H1s + (ar + 16) * 136 + ac));
            int br = kk * 16 + (lane & 15);
#pragma unroll
            for (int p = 0; p < 2; ++p) {
                unsigned bb[4];
                ldm_x4t(bb, cvta_s(W2C[b] + br * 72 + wn * 32 + p * 16 + (lane >> 4) * 8));
                mma16816(acc2[0][2 * p],     a0, bb[0], bb[1]);
                mma16816(acc2[1][2 * p],     a1, bb[0], bb[1]);
                mma16816(acc2[0][2 * p + 1], a0, bb[2], bb[3]);
                mma16816(acc2[1][2 * p + 1], a1, bb[2], bb[3]);
            }
        }
        __syncthreads();
        if (ch + 2 < 4) issueW2(ch + 2, b);
        cp_commit();
    }

    // epilogue GEMM2: bias + relu -> H2s (fp32)
    {
        const float* b2 = eb2 + e * HH2;
#pragma unroll
        for (int mi = 0; mi < 2; ++mi)
#pragma unroll
            for (int nj = 0; nj < 4; ++nj) {
                int r = wm * 32 + mi * 16 + (lane >> 2);
                int c = wn * 32 + nj * 8 + (lane & 3) * 2;
                float ba = b2[c], bbv = b2[c + 1];
                H2s[r * 67 + c]           = fmaxf(acc2[mi][nj][0] + ba,  0.f);
                H2s[r * 67 + c + 1]       = fmaxf(acc2[mi][nj][1] + bbv, 0.f);
                H2s[(r + 8) * 67 + c]     = fmaxf(acc2[mi][nj][2] + ba,  0.f);
                H2s[(r + 8) * 67 + c + 1] = fmaxf(acc2[mi][nj][3] + bbv, 0.f);
            }
    }
    __syncthreads();

    // GEMM3 + sigmoid
    {
        int row = tid >> 1, half = tid & 1;
        const float* w3 = eW3 + e * HH2 + half * 32;
        const float* hp = H2s + row * 67 + half * 32;
        float s = 0.f;
#pragma unroll
        for (int i = 0; i < 32; ++i) s += hp[i] * w3[i];
        s += __shfl_xor_sync(0xffffffffu, s, 1);
        if (half == 0) {
            float z = s + eb3[e];
            out[(size_t)BN * 17 + (size_t)(m0 + row) * EE + e] = 1.f / (1.f + expf(-z));
        }
    }
}

// ---------------- combine ----------------
__global__ void combine_kernel(float* __restrict__ out) {
    int i = blockIdx.x * 256 + threadIdx.x;
    const float4* rw = (const float4*)(out + BN + (size_t)i * EE);
    const float4* eo = (const float4*)(out + (size_t)BN * 17 + (size_t)i * EE);
    float s = 0.f;
#pragma unroll
    for (int q = 0; q < 4; ++q) {
        float4 a = rw[q], b = eo[q];
        s += a.x * b.x + a.y * b.y + a.z * b.z + a.w * b.w;
    }
    out[i] = s;
}

// ---------------- launcher ----------------
extern "C" void kernel_launch(void* const* d_in, const int* in_sizes, int n_in,
                              void* d_out, int out_size) {
    const float* x       = (const float*)d_in[0];
    const float* r_gamma = (const float*)d_in[1];
    const float* r_beta  = (const float*)d_in[2];
    const float* r_mean  = (const float*)d_in[3];
    const float* r_var   = (const float*)d_in[4];
    const float* rW1     = (const float*)d_in[5];
    const float* rb1     = (const float*)d_in[6];
    const float* rW2     = (const float*)d_in[7];
    const float* rb2     = (const float*)d_in[8];
    const float* rW3     = (const float*)d_in[9];
    const float* rb3     = (const float*)d_in[10];
    const float* e_gamma = (const float*)d_in[11];
    const float* e_beta  = (const float*)d_in[12];
    const float* e_mean  = (const float*)d_in[13];
    const float* e_var   = (const float*)d_in[14];
    const float* eW1     = (const float*)d_in[15];
    const float* eb1     = (const float*)d_in[16];
    const float* eW2     = (const float*)d_in[17];
    const float* eb2     = (const float*)d_in[18];
    const float* eW3     = (const float*)d_in[19];
    const float* eb3     = (const float*)d_in[20];
    float* out = (float*)d_out;

    k_conv_x<<<(BN * (size_t)DD) / (256 * 8), 256>>>(x);                     // launch 0
    k_prep_router<<<320, 256>>>(rW1, r_gamma, r_beta, r_mean, r_var, rb1);   // launch 1
    k_prep_expert_w<<<8704, 256>>>(eW1, e_gamma, e_var, eW2);                // launch 2
    k_fold_expert_b<<<EE * HH1, 256>>>(eW1, e_gamma, e_beta, e_mean, e_var, eb1); // 3
    router_kernel<<<BN / 128, 256>>>(rW2, rb2, rW3, rb3, out);               // launch 4
    expert_kernel<<<dim3(EE, BN / 128), 256>>>(eb2, eW3, eb3, out);          // launch 5 (profiled)
    combine_kernel<<<BN / 256, 256>>>(out);                                  // launch 6
}